// round 2
// baseline (speedup 1.0000x reference)
#include <cuda_runtime.h>

// Problem constants
#define B_TOT    4096
#define T_LEN    512
#define D_IN     7
#define H        64
#define G        256      // 4*H gates per layer
#define OUT_D    4
#define BTILE    32       // batch rows per CTA (lane = row)
#define NTHREADS 1024     // 32 warps: warp = 2 hidden units
#define HPITCH   68       // h smem pitch in floats (conflict-free for LDS.128)

typedef unsigned long long u64;

__device__ __forceinline__ u64 pack2(float v) {
    u64 r; asm("mov.b64 %0, {%1, %1};" : "=l"(r) : "f"(v)); return r;
}
__device__ __forceinline__ void unpack2(u64 v, float& a, float& b) {
    asm("mov.b64 {%0, %1}, %2;" : "=f"(a), "=f"(b) : "l"(v));
}
__device__ __forceinline__ u64 ffma2(u64 a, u64 b, u64 c) {
    u64 d; asm("fma.rn.f32x2 %0, %1, %2, %3;" : "=l"(d) : "l"(a), "l"(b), "l"(c)); return d;
}

__device__ __forceinline__ float sigf(float x) {
    return __fdividef(1.0f, 1.0f + __expf(-x));
}
__device__ __forceinline__ float tanhf_fast(float x) {
    return __fdividef(2.0f, 1.0f + __expf(-2.0f * x)) - 1.0f;
}

__global__ __launch_bounds__(NTHREADS, 1)
void lstm_fused_kernel(const float* __restrict__ x,
                       const float* __restrict__ W_ih0, const float* __restrict__ W_hh0,
                       const float* __restrict__ b_ih0, const float* __restrict__ b_hh0,
                       const float* __restrict__ W_ih1, const float* __restrict__ W_hh1,
                       const float* __restrict__ b_ih1, const float* __restrict__ b_hh1,
                       const float* __restrict__ W_fc,  const float* __restrict__ b_fc,
                       float* __restrict__ out)
{
    extern __shared__ float smem[];
    // weight layout: [k][unit][gate i,f,g,o]  -> idx = k*256 + u*4 + gb
    float* s_wih0 = smem;                    // [7][256]
    float* s_whh0 = s_wih0 + D_IN * G;       // [64][256]
    float* s_wih1 = s_whh0 + H * G;          // [64][256]
    float* s_whh1 = s_wih1 + H * G;          // [64][256]
    float* s_b0   = s_whh1 + H * G;          // [256]  combined bias, [u][gb]
    float* s_b1   = s_b0 + G;                // [256]
    float* s_wfc  = s_b1 + G;                // [4][64]
    float* s_bfc  = s_wfc + OUT_D * H;       // [8]
    float* s_h0   = s_bfc + 8;               // [32][HPITCH]  h layer0, [row][k]
    float* s_h1   = s_h0 + BTILE * HPITCH;   // [32][HPITCH]

    const int tid  = threadIdx.x;
    const int lane = tid & 31;               // batch row within tile
    const int w    = tid >> 5;               // warp id 0..31
    const int u0   = w * 2;                  // this warp's 2 hidden units

    // ---- stage weights into smem, transposed + gate-interleaved ----
    for (int idx = tid; idx < D_IN * G; idx += NTHREADS) {
        int d = idx >> 8, r = idx & 255, u = r >> 2, gb = r & 3;
        s_wih0[idx] = W_ih0[(gb * H + u) * D_IN + d];
    }
    for (int idx = tid; idx < H * G; idx += NTHREADS) {
        int k = idx >> 8, r = idx & 255, u = r >> 2, gb = r & 3;
        int row = gb * H + u;
        s_whh0[idx] = W_hh0[row * H + k];
        s_wih1[idx] = W_ih1[row * H + k];
        s_whh1[idx] = W_hh1[row * H + k];
    }
    for (int r = tid; r < G; r += NTHREADS) {
        int u = r >> 2, gb = r & 3, row = gb * H + u;
        s_b0[r] = b_ih0[row] + b_hh0[row];
        s_b1[r] = b_ih1[row] + b_hh1[row];
    }
    for (int i = tid; i < OUT_D * H; i += NTHREADS) s_wfc[i] = W_fc[i];
    if (tid < OUT_D) s_bfc[tid] = b_fc[tid];
    for (int i = tid; i < BTILE * HPITCH; i += NTHREADS) { s_h0[i] = 0.0f; s_h1[i] = 0.0f; }
    __syncthreads();

    float c0[2] = {0.f, 0.f};
    float c1[2] = {0.f, 0.f};

    const int b = blockIdx.x * BTILE + lane;
    const float* xb  = x + (size_t)b * T_LEN * D_IN;
    const float* hb0 = s_h0 + lane * HPITCH;
    const float* hb1 = s_h1 + lane * HPITCH;

    for (int t = 0; t < T_LEN; t++) {
        // issue x loads early; consumed after the long k-loop
        float xr[D_IN];
        #pragma unroll
        for (int d = 0; d < D_IN; d++) xr[d] = __ldg(xb + t * D_IN + d);

        // accumulators as f32x2 pairs: a[0]=(i,f) u0, a[1]=(g,o) u0, a[2]=(i,f) u0+1, a[3]=(g,o) u0+1
        u64 a0[4], a1[4];
        {
            ulonglong2 t0 = *(const ulonglong2*)&s_b0[u0 * 4];
            ulonglong2 t1 = *(const ulonglong2*)&s_b0[u0 * 4 + 4];
            a0[0] = t0.x; a0[1] = t0.y; a0[2] = t1.x; a0[3] = t1.y;
            ulonglong2 t2 = *(const ulonglong2*)&s_b1[u0 * 4];
            ulonglong2 t3 = *(const ulonglong2*)&s_b1[u0 * 4 + 4];
            a1[0] = t2.x; a1[1] = t2.y; a1[2] = t3.x; a1[3] = t3.y;
        }

        // ---- phase 1: h0 @ W_hh0^T and h1 @ W_hh1^T (h batched as float4) ----
        #pragma unroll 2
        for (int kb = 0; kb < H; kb += 4) {
            float4 h0v4 = *(const float4*)&hb0[kb];
            float4 h1v4 = *(const float4*)&hb1[kb];
            float h0s[4] = {h0v4.x, h0v4.y, h0v4.z, h0v4.w};
            float h1s[4] = {h1v4.x, h1v4.y, h1v4.z, h1v4.w};
            #pragma unroll
            for (int j = 0; j < 4; j++) {
                int k = kb + j;
                u64 h0p = pack2(h0s[j]);
                u64 h1p = pack2(h1s[j]);
                ulonglong2 w0a = *(const ulonglong2*)&s_whh0[k * G + u0 * 4];
                ulonglong2 w0b = *(const ulonglong2*)&s_whh0[k * G + u0 * 4 + 4];
                ulonglong2 w1a = *(const ulonglong2*)&s_whh1[k * G + u0 * 4];
                ulonglong2 w1b = *(const ulonglong2*)&s_whh1[k * G + u0 * 4 + 4];
                a0[0] = ffma2(w0a.x, h0p, a0[0]);
                a0[1] = ffma2(w0a.y, h0p, a0[1]);
                a0[2] = ffma2(w0b.x, h0p, a0[2]);
                a0[3] = ffma2(w0b.y, h0p, a0[3]);
                a1[0] = ffma2(w1a.x, h1p, a1[0]);
                a1[1] = ffma2(w1a.y, h1p, a1[1]);
                a1[2] = ffma2(w1b.x, h1p, a1[2]);
                a1[3] = ffma2(w1b.y, h1p, a1[3]);
            }
        }

        // x @ W_ih0^T (x loads have had the whole k-loop to land)
        #pragma unroll
        for (int d = 0; d < D_IN; d++) {
            u64 xv = pack2(xr[d]);
            ulonglong2 wa = *(const ulonglong2*)&s_wih0[d * G + u0 * 4];
            ulonglong2 wb = *(const ulonglong2*)&s_wih0[d * G + u0 * 4 + 4];
            a0[0] = ffma2(wa.x, xv, a0[0]);
            a0[1] = ffma2(wa.y, xv, a0[1]);
            a0[2] = ffma2(wb.x, xv, a0[2]);
            a0[3] = ffma2(wb.y, xv, a0[3]);
        }

        // layer-0 cell update
        float h0n[2];
        #pragma unroll
        for (int j = 0; j < 2; j++) {
            float gi, gf, gg, go;
            unpack2(a0[2 * j],     gi, gf);
            unpack2(a0[2 * j + 1], gg, go);
            float i_ = sigf(gi), f_ = sigf(gf), g_ = tanhf_fast(gg), o_ = sigf(go);
            c0[j] = f_ * c0[j] + i_ * g_;
            h0n[j] = o_ * tanhf_fast(c0[j]);
        }

        __syncthreads();   // everyone done reading s_h0/s_h1 for this step
        s_h0[lane * HPITCH + u0]     = h0n[0];
        s_h0[lane * HPITCH + u0 + 1] = h0n[1];
        __syncthreads();   // new h0 visible

        // ---- phase 2: h0(new) @ W_ih1^T ----
        #pragma unroll 2
        for (int kb = 0; kb < H; kb += 4) {
            float4 hv4 = *(const float4*)&hb0[kb];
            float hs[4] = {hv4.x, hv4.y, hv4.z, hv4.w};
            #pragma unroll
            for (int j = 0; j < 4; j++) {
                int k = kb + j;
                u64 hp = pack2(hs[j]);
                ulonglong2 wa = *(const ulonglong2*)&s_wih1[k * G + u0 * 4];
                ulonglong2 wb = *(const ulonglong2*)&s_wih1[k * G + u0 * 4 + 4];
                a1[0] = ffma2(wa.x, hp, a1[0]);
                a1[1] = ffma2(wa.y, hp, a1[1]);
                a1[2] = ffma2(wb.x, hp, a1[2]);
                a1[3] = ffma2(wb.y, hp, a1[3]);
            }
        }

        // layer-1 cell update; phase 2 never reads s_h1, so writing now is safe
        #pragma unroll
        for (int j = 0; j < 2; j++) {
            float gi, gf, gg, go;
            unpack2(a1[2 * j],     gi, gf);
            unpack2(a1[2 * j + 1], gg, go);
            float i_ = sigf(gi), f_ = sigf(gf), g_ = tanhf_fast(gg), o_ = sigf(go);
            c1[j] = f_ * c1[j] + i_ * g_;
            s_h1[lane * HPITCH + u0 + j] = o_ * tanhf_fast(c1[j]);
        }
        __syncthreads();   // h1 complete before next step reads it
    }

    // ---- epilogue: out[b] = h1_last @ W_fc^T + b_fc (warp 0) ----
    if (tid < 32) {
        float acc[OUT_D];
        #pragma unroll
        for (int o = 0; o < OUT_D; o++) acc[o] = s_bfc[o];
        #pragma unroll 8
        for (int k = 0; k < H; k++) {
            float hv = s_h1[lane * HPITCH + k];
            #pragma unroll
            for (int o = 0; o < OUT_D; o++) acc[o] += hv * s_wfc[o * H + k];
        }
        #pragma unroll
        for (int o = 0; o < OUT_D; o++)
            out[(size_t)b * OUT_D + o] = acc[o];
    }
}

extern "C" void kernel_launch(void* const* d_in, const int* in_sizes, int n_in,
                              void* d_out, int out_size)
{
    const float* x     = (const float*)d_in[0];
    const float* W_ih0 = (const float*)d_in[1];
    const float* W_hh0 = (const float*)d_in[2];
    const float* b_ih0 = (const float*)d_in[3];
    const float* b_hh0 = (const float*)d_in[4];
    const float* W_ih1 = (const float*)d_in[5];
    const float* W_hh1 = (const float*)d_in[6];
    const float* b_ih1 = (const float*)d_in[7];
    const float* b_hh1 = (const float*)d_in[8];
    const float* W_fc  = (const float*)d_in[9];
    const float* b_fc  = (const float*)d_in[10];
    float* out = (float*)d_out;

    const size_t smem_floats = (size_t)D_IN * G + 3 * (size_t)H * G + 2 * G
                             + OUT_D * H + 8 + 2 * (size_t)BTILE * HPITCH;
    const size_t smem_bytes = smem_floats * sizeof(float);   // 224,288 B

    cudaFuncSetAttribute(lstm_fused_kernel,
                         cudaFuncAttributeMaxDynamicSharedMemorySize,
                         (int)smem_bytes);

    lstm_fused_kernel<<<B_TOT / BTILE, NTHREADS, smem_bytes>>>(
        x, W_ih0, W_hh0, b_ih0, b_hh0,
        W_ih1, W_hh1, b_ih1, b_hh1, W_fc, b_fc, out);
}

// round 3
// speedup vs baseline: 1.1973x; 1.1973x over previous
#include <cuda_runtime.h>

// Problem constants
#define B_TOT    4096
#define T_LEN    512
#define D_IN     7
#define H        64
#define G        256      // 4*H gates per layer
#define OUT_D    4
#define BTILE    32       // batch rows per CTA (lane = row)
#define NTHREADS 512      // 16 warps: warp = 4 hidden units
#define HPITCH   68       // h smem pitch in floats (conflict-free for LDS.128)

typedef unsigned long long u64;

__device__ __forceinline__ u64 pack2(float v) {
    u64 r; asm("mov.b64 %0, {%1, %1};" : "=l"(r) : "f"(v)); return r;
}
__device__ __forceinline__ void unpack2(u64 v, float& a, float& b) {
    asm("mov.b64 {%0, %1}, %2;" : "=f"(a), "=f"(b) : "l"(v));
}
__device__ __forceinline__ u64 ffma2(u64 a, u64 b, u64 c) {
    u64 d; asm("fma.rn.f32x2 %0, %1, %2, %3;" : "=l"(d) : "l"(a), "l"(b), "l"(c)); return d;
}

__device__ __forceinline__ float sigf(float x) {
    return __fdividef(1.0f, 1.0f + __expf(-x));
}
__device__ __forceinline__ float tanhf_fast(float x) {
    return __fdividef(2.0f, 1.0f + __expf(-2.0f * x)) - 1.0f;
}

__global__ __launch_bounds__(NTHREADS, 1)
void lstm_fused_kernel(const float* __restrict__ x,
                       const float* __restrict__ W_ih0, const float* __restrict__ W_hh0,
                       const float* __restrict__ b_ih0, const float* __restrict__ b_hh0,
                       const float* __restrict__ W_ih1, const float* __restrict__ W_hh1,
                       const float* __restrict__ b_ih1, const float* __restrict__ b_hh1,
                       const float* __restrict__ W_fc,  const float* __restrict__ b_fc,
                       float* __restrict__ out)
{
    extern __shared__ float smem[];
    // weight layout: [k][unit][gate i,f,g,o]  -> idx = k*256 + u*4 + gb
    float* s_wih0 = smem;                    // [7][256]
    float* s_whh0 = s_wih0 + D_IN * G;       // [64][256]
    float* s_wih1 = s_whh0 + H * G;          // [64][256]
    float* s_whh1 = s_wih1 + H * G;          // [64][256]
    float* s_b0   = s_whh1 + H * G;          // [256]  combined bias, [u][gb]
    float* s_b1   = s_b0 + G;                // [256]
    float* s_wfc  = s_b1 + G;                // [4][64]
    float* s_bfc  = s_wfc + OUT_D * H;       // [8]
    float* s_h0   = s_bfc + 8;               // [32][HPITCH]  h layer0, [row][k]
    float* s_h1   = s_h0 + BTILE * HPITCH;   // [32][HPITCH]

    const int tid  = threadIdx.x;
    const int lane = tid & 31;               // batch row within tile
    const int w    = tid >> 5;               // warp id 0..15
    const int u0   = w * 4;                  // this warp's 4 hidden units

    // ---- stage weights into smem, transposed + gate-interleaved ----
    for (int idx = tid; idx < D_IN * G; idx += NTHREADS) {
        int d = idx >> 8, r = idx & 255, u = r >> 2, gb = r & 3;
        s_wih0[idx] = W_ih0[(gb * H + u) * D_IN + d];
    }
    for (int idx = tid; idx < H * G; idx += NTHREADS) {
        int k = idx >> 8, r = idx & 255, u = r >> 2, gb = r & 3;
        int row = gb * H + u;
        s_whh0[idx] = W_hh0[row * H + k];
        s_wih1[idx] = W_ih1[row * H + k];
        s_whh1[idx] = W_hh1[row * H + k];
    }
    for (int r = tid; r < G; r += NTHREADS) {
        int u = r >> 2, gb = r & 3, row = gb * H + u;
        s_b0[r] = b_ih0[row] + b_hh0[row];
        s_b1[r] = b_ih1[row] + b_hh1[row];
    }
    for (int i = tid; i < OUT_D * H; i += NTHREADS) s_wfc[i] = W_fc[i];
    if (tid < OUT_D) s_bfc[tid] = b_fc[tid];
    for (int i = tid; i < BTILE * HPITCH; i += NTHREADS) { s_h0[i] = 0.0f; s_h1[i] = 0.0f; }
    __syncthreads();

    float c0[4] = {0.f, 0.f, 0.f, 0.f};
    float c1[4] = {0.f, 0.f, 0.f, 0.f};

    const int b = blockIdx.x * BTILE + lane;
    const float* xb  = x + (size_t)b * T_LEN * D_IN;
    const float* hb0 = s_h0 + lane * HPITCH;
    const float* hb1 = s_h1 + lane * HPITCH;

    for (int t = 0; t < T_LEN; t++) {
        // issue x loads early; consumed after the long k-loop
        float xr[D_IN];
        #pragma unroll
        for (int d = 0; d < D_IN; d++) xr[d] = __ldg(xb + t * D_IN + d);

        // accumulators: a[2j]=(i,f) unit u0+j, a[2j+1]=(g,o) unit u0+j
        u64 a0[8], a1[8];
        {
            #pragma unroll
            for (int j = 0; j < 4; j++) {
                ulonglong2 t0 = *(const ulonglong2*)&s_b0[u0 * 4 + j * 4];
                a0[2*j] = t0.x; a0[2*j+1] = t0.y;
                ulonglong2 t1 = *(const ulonglong2*)&s_b1[u0 * 4 + j * 4];
                a1[2*j] = t1.x; a1[2*j+1] = t1.y;
            }
        }

        // ---- phase 1: h0 @ W_hh0^T and h1 @ W_hh1^T ----
        for (int kb = 0; kb < H; kb += 4) {
            float4 h0v4 = *(const float4*)&hb0[kb];
            float4 h1v4 = *(const float4*)&hb1[kb];
            float h0s[4] = {h0v4.x, h0v4.y, h0v4.z, h0v4.w};
            float h1s[4] = {h1v4.x, h1v4.y, h1v4.z, h1v4.w};
            #pragma unroll
            for (int j = 0; j < 4; j++) {
                int k = kb + j;
                u64 h0p = pack2(h0s[j]);
                u64 h1p = pack2(h1s[j]);
                const float* w0base = &s_whh0[k * G + u0 * 4];
                const float* w1base = &s_whh1[k * G + u0 * 4];
                ulonglong2 w0a = *(const ulonglong2*)(w0base);
                ulonglong2 w0b = *(const ulonglong2*)(w0base + 4);
                ulonglong2 w0c = *(const ulonglong2*)(w0base + 8);
                ulonglong2 w0d = *(const ulonglong2*)(w0base + 12);
                ulonglong2 w1a = *(const ulonglong2*)(w1base);
                ulonglong2 w1b = *(const ulonglong2*)(w1base + 4);
                ulonglong2 w1c = *(const ulonglong2*)(w1base + 8);
                ulonglong2 w1d = *(const ulonglong2*)(w1base + 12);
                a0[0] = ffma2(w0a.x, h0p, a0[0]);
                a0[1] = ffma2(w0a.y, h0p, a0[1]);
                a0[2] = ffma2(w0b.x, h0p, a0[2]);
                a0[3] = ffma2(w0b.y, h0p, a0[3]);
                a0[4] = ffma2(w0c.x, h0p, a0[4]);
                a0[5] = ffma2(w0c.y, h0p, a0[5]);
                a0[6] = ffma2(w0d.x, h0p, a0[6]);
                a0[7] = ffma2(w0d.y, h0p, a0[7]);
                a1[0] = ffma2(w1a.x, h1p, a1[0]);
                a1[1] = ffma2(w1a.y, h1p, a1[1]);
                a1[2] = ffma2(w1b.x, h1p, a1[2]);
                a1[3] = ffma2(w1b.y, h1p, a1[3]);
                a1[4] = ffma2(w1c.x, h1p, a1[4]);
                a1[5] = ffma2(w1c.y, h1p, a1[5]);
                a1[6] = ffma2(w1d.x, h1p, a1[6]);
                a1[7] = ffma2(w1d.y, h1p, a1[7]);
            }
        }

        // x @ W_ih0^T
        #pragma unroll
        for (int d = 0; d < D_IN; d++) {
            u64 xv = pack2(xr[d]);
            const float* wbase = &s_wih0[d * G + u0 * 4];
            ulonglong2 wa = *(const ulonglong2*)(wbase);
            ulonglong2 wb = *(const ulonglong2*)(wbase + 4);
            ulonglong2 wc = *(const ulonglong2*)(wbase + 8);
            ulonglong2 wd = *(const ulonglong2*)(wbase + 12);
            a0[0] = ffma2(wa.x, xv, a0[0]);
            a0[1] = ffma2(wa.y, xv, a0[1]);
            a0[2] = ffma2(wb.x, xv, a0[2]);
            a0[3] = ffma2(wb.y, xv, a0[3]);
            a0[4] = ffma2(wc.x, xv, a0[4]);
            a0[5] = ffma2(wc.y, xv, a0[5]);
            a0[6] = ffma2(wd.x, xv, a0[6]);
            a0[7] = ffma2(wd.y, xv, a0[7]);
        }

        // layer-0 cell update
        float4 h0n;
        float* h0np = (float*)&h0n;
        #pragma unroll
        for (int j = 0; j < 4; j++) {
            float gi, gf, gg, go;
            unpack2(a0[2*j],   gi, gf);
            unpack2(a0[2*j+1], gg, go);
            float i_ = sigf(gi), f_ = sigf(gf), g_ = tanhf_fast(gg), o_ = sigf(go);
            c0[j] = f_ * c0[j] + i_ * g_;
            h0np[j] = o_ * tanhf_fast(c0[j]);
        }

        __syncthreads();   // everyone done reading s_h0/s_h1 for this step
        *(float4*)&s_h0[lane * HPITCH + u0] = h0n;
        __syncthreads();   // new h0 visible

        // ---- phase 2: h0(new) @ W_ih1^T ----
        for (int kb = 0; kb < H; kb += 4) {
            float4 hv4 = *(const float4*)&hb0[kb];
            float hs[4] = {hv4.x, hv4.y, hv4.z, hv4.w};
            #pragma unroll
            for (int j = 0; j < 4; j++) {
                int k = kb + j;
                u64 hp = pack2(hs[j]);
                const float* wbase = &s_wih1[k * G + u0 * 4];
                ulonglong2 wa = *(const ulonglong2*)(wbase);
                ulonglong2 wb = *(const ulonglong2*)(wbase + 4);
                ulonglong2 wc = *(const ulonglong2*)(wbase + 8);
                ulonglong2 wd = *(const ulonglong2*)(wbase + 12);
                a1[0] = ffma2(wa.x, hp, a1[0]);
                a1[1] = ffma2(wa.y, hp, a1[1]);
                a1[2] = ffma2(wb.x, hp, a1[2]);
                a1[3] = ffma2(wb.y, hp, a1[3]);
                a1[4] = ffma2(wc.x, hp, a1[4]);
                a1[5] = ffma2(wc.y, hp, a1[5]);
                a1[6] = ffma2(wd.x, hp, a1[6]);
                a1[7] = ffma2(wd.y, hp, a1[7]);
            }
        }

        // layer-1 cell update; phase 2 never reads s_h1, so writing now is safe
        float4 h1n;
        float* h1np = (float*)&h1n;
        #pragma unroll
        for (int j = 0; j < 4; j++) {
            float gi, gf, gg, go;
            unpack2(a1[2*j],   gi, gf);
            unpack2(a1[2*j+1], gg, go);
            float i_ = sigf(gi), f_ = sigf(gf), g_ = tanhf_fast(gg), o_ = sigf(go);
            c1[j] = f_ * c1[j] + i_ * g_;
            h1np[j] = o_ * tanhf_fast(c1[j]);
        }
        *(float4*)&s_h1[lane * HPITCH + u0] = h1n;
        __syncthreads();   // h1 complete before next step reads it
    }

    // ---- epilogue: out[b] = h1_last @ W_fc^T + b_fc (warp 0) ----
    if (tid < 32) {
        float acc[OUT_D];
        #pragma unroll
        for (int o = 0; o < OUT_D; o++) acc[o] = s_bfc[o];
        #pragma unroll 8
        for (int k = 0; k < H; k++) {
            float hv = s_h1[lane * HPITCH + k];
            #pragma unroll
            for (int o = 0; o < OUT_D; o++) acc[o] += hv * s_wfc[o * H + k];
        }
        #pragma unroll
        for (int o = 0; o < OUT_D; o++)
            out[(size_t)b * OUT_D + o] = acc[o];
    }
}

extern "C" void kernel_launch(void* const* d_in, const int* in_sizes, int n_in,
                              void* d_out, int out_size)
{
    const float* x     = (const float*)d_in[0];
    const float* W_ih0 = (const float*)d_in[1];
    const float* W_hh0 = (const float*)d_in[2];
    const float* b_ih0 = (const float*)d_in[3];
    const float* b_hh0 = (const float*)d_in[4];
    const float* W_ih1 = (const float*)d_in[5];
    const float* W_hh1 = (const float*)d_in[6];
    const float* b_ih1 = (const float*)d_in[7];
    const float* b_hh1 = (const float*)d_in[8];
    const float* W_fc  = (const float*)d_in[9];
    const float* b_fc  = (const float*)d_in[10];
    float* out = (float*)d_out;

    const size_t smem_floats = (size_t)D_IN * G + 3 * (size_t)H * G + 2 * G
                             + OUT_D * H + 8 + 2 * (size_t)BTILE * HPITCH;
    const size_t smem_bytes = smem_floats * sizeof(float);   // 224,288 B

    cudaFuncSetAttribute(lstm_fused_kernel,
                         cudaFuncAttributeMaxDynamicSharedMemorySize,
                         (int)smem_bytes);

    lstm_fused_kernel<<<B_TOT / BTILE, NTHREADS, smem_bytes>>>(
        x, W_ih0, W_hh0, b_ih0, b_hh0,
        W_ih1, W_hh1, b_ih1, b_hh1, W_fc, b_fc, out);
}

// round 4
// speedup vs baseline: 1.8019x; 1.5049x over previous
#include <cuda_runtime.h>

// Problem constants
#define B_TOT    4096
#define T_LEN    512
#define D_IN     7
#define H        64
#define G        256      // 4*H gates per layer
#define OUT_D    4
#define BTILE    32       // batch rows per CTA
#define NTHREADS 512      // thread = (4 batch rows) x (1 unit = 4 gates)
#define RP       36       // h smem pitch in floats (conflict-free, 16B-aligned rows)

typedef unsigned long long u64;

__device__ __forceinline__ u64 pack2(float v) {
    u64 r; asm("mov.b64 %0, {%1, %1};" : "=l"(r) : "f"(v)); return r;
}
__device__ __forceinline__ void unpack2(u64 v, float& a, float& b) {
    asm("mov.b64 {%0, %1}, %2;" : "=f"(a), "=f"(b) : "l"(v));
}
__device__ __forceinline__ u64 ffma2(u64 a, u64 b, u64 c) {
    u64 d; asm("fma.rn.f32x2 %0, %1, %2, %3;" : "=l"(d) : "l"(a), "l"(b), "l"(c)); return d;
}

__device__ __forceinline__ float sigf(float x) {
    return __fdividef(1.0f, 1.0f + __expf(-x));
}
__device__ __forceinline__ float tanhf_fast(float x) {
    return __fdividef(2.0f, 1.0f + __expf(-2.0f * x)) - 1.0f;
}

__global__ __launch_bounds__(NTHREADS, 1)
void lstm_fused_kernel(const float* __restrict__ x,
                       const float* __restrict__ W_ih0, const float* __restrict__ W_hh0,
                       const float* __restrict__ b_ih0, const float* __restrict__ b_hh0,
                       const float* __restrict__ W_ih1, const float* __restrict__ W_hh1,
                       const float* __restrict__ b_ih1, const float* __restrict__ b_hh1,
                       const float* __restrict__ W_fc,  const float* __restrict__ b_fc,
                       float* __restrict__ out)
{
    extern __shared__ float smem[];
    // weight layout: [k][unit][gate i,f,g,o] -> idx = k*256 + u*4 + g
    float* s_wih0 = smem;                    // [7][256]
    float* s_whh0 = s_wih0 + D_IN * G;       // [64][256]
    float* s_wih1 = s_whh0 + H * G;          // [64][256]
    float* s_whh1 = s_wih1 + H * G;          // [64][256]
    float* s_b0   = s_whh1 + H * G;          // [256]  combined bias [u][g]
    float* s_b1   = s_b0 + G;                // [256]
    float* s_wfc  = s_b1 + G;                // [4][64]
    float* s_bfc  = s_wfc + OUT_D * H;       // [8]
    float* s_h0   = s_bfc + 8;               // [64][RP]  h layer0, [unit][row]
    float* s_h1   = s_h0 + H * RP;           // [64][RP]

    const int tid  = threadIdx.x;
    const int urow = tid >> 6;               // 0..7 : batch-row group
    const int ucol = tid & 63;               // 0..63: hidden unit
    const int r0   = urow * 4;               // first of this thread's 4 rows

    // ---- stage weights into smem, transposed + gate-interleaved ----
    for (int idx = tid; idx < D_IN * G; idx += NTHREADS) {
        int d = idx >> 8, r = idx & 255, u = r >> 2, gb = r & 3;
        s_wih0[idx] = W_ih0[(gb * H + u) * D_IN + d];
    }
    for (int idx = tid; idx < H * G; idx += NTHREADS) {
        int k = idx >> 8, r = idx & 255, u = r >> 2, gb = r & 3;
        int row = gb * H + u;
        s_whh0[idx] = W_hh0[row * H + k];
        s_wih1[idx] = W_ih1[row * H + k];
        s_whh1[idx] = W_hh1[row * H + k];
    }
    for (int r = tid; r < G; r += NTHREADS) {
        int u = r >> 2, gb = r & 3, row = gb * H + u;
        s_b0[r] = b_ih0[row] + b_hh0[row];
        s_b1[r] = b_ih1[row] + b_hh1[row];
    }
    for (int i = tid; i < OUT_D * H; i += NTHREADS) s_wfc[i] = W_fc[i];
    if (tid < OUT_D) s_bfc[tid] = b_fc[tid];
    for (int i = tid; i < H * RP; i += NTHREADS) { s_h0[i] = 0.0f; s_h1[i] = 0.0f; }
    __syncthreads();

    // bias pairs for this thread's unit, held in regs across all steps
    u64 b0p0, b0p1, b1p0, b1p1;
    {
        ulonglong2 t0 = *(const ulonglong2*)&s_b0[ucol * 4];
        b0p0 = t0.x; b0p1 = t0.y;
        ulonglong2 t1 = *(const ulonglong2*)&s_b1[ucol * 4];
        b1p0 = t1.x; b1p1 = t1.y;
    }

    float c0[4] = {0.f, 0.f, 0.f, 0.f};
    float c1[4] = {0.f, 0.f, 0.f, 0.f};

    const int bbase = blockIdx.x * BTILE + r0;
    const float* xr0 = x + (size_t)(bbase + 0) * T_LEN * D_IN;
    const float* xr1 = x + (size_t)(bbase + 1) * T_LEN * D_IN;
    const float* xr2 = x + (size_t)(bbase + 2) * T_LEN * D_IN;
    const float* xr3 = x + (size_t)(bbase + 3) * T_LEN * D_IN;

    for (int t = 0; t < T_LEN; t++) {
        // prefetch x for this step's 4 rows (consumed after the k-loop)
        float xv[4][D_IN];
        #pragma unroll
        for (int d = 0; d < D_IN; d++) {
            xv[0][d] = __ldg(xr0 + t * D_IN + d);
            xv[1][d] = __ldg(xr1 + t * D_IN + d);
            xv[2][d] = __ldg(xr2 + t * D_IN + d);
            xv[3][d] = __ldg(xr3 + t * D_IN + d);
        }

        // accumulators: a0[2r]=(i,f), a0[2r+1]=(g,o) for row r0+r
        u64 a0[8], a1[8];
        #pragma unroll
        for (int r = 0; r < 4; r++) {
            a0[2*r] = b0p0; a0[2*r+1] = b0p1;
            a1[2*r] = b1p0; a1[2*r+1] = b1p1;
        }

        // ---- phase 1: h0 @ W_hh0^T and h1 @ W_hh1^T ----
        #pragma unroll 4
        for (int k = 0; k < H; k++) {
            ulonglong2 w0 = *(const ulonglong2*)&s_whh0[k * G + ucol * 4];
            ulonglong2 w1 = *(const ulonglong2*)&s_whh1[k * G + ucol * 4];
            float4 h0v = *(const float4*)&s_h0[k * RP + r0];
            float4 h1v = *(const float4*)&s_h1[k * RP + r0];
            float h0s[4] = {h0v.x, h0v.y, h0v.z, h0v.w};
            float h1s[4] = {h1v.x, h1v.y, h1v.z, h1v.w};
            #pragma unroll
            for (int r = 0; r < 4; r++) {
                u64 h0p = pack2(h0s[r]);
                a0[2*r]   = ffma2(w0.x, h0p, a0[2*r]);
                a0[2*r+1] = ffma2(w0.y, h0p, a0[2*r+1]);
                u64 h1p = pack2(h1s[r]);
                a1[2*r]   = ffma2(w1.x, h1p, a1[2*r]);
                a1[2*r+1] = ffma2(w1.y, h1p, a1[2*r+1]);
            }
        }

        // x @ W_ih0^T
        #pragma unroll
        for (int d = 0; d < D_IN; d++) {
            ulonglong2 w = *(const ulonglong2*)&s_wih0[d * G + ucol * 4];
            #pragma unroll
            for (int r = 0; r < 4; r++) {
                u64 xp = pack2(xv[r][d]);
                a0[2*r]   = ffma2(w.x, xp, a0[2*r]);
                a0[2*r+1] = ffma2(w.y, xp, a0[2*r+1]);
            }
        }

        // layer-0 cell update for 4 rows of unit ucol
        float4 h0n;
        float* h0np = (float*)&h0n;
        #pragma unroll
        for (int r = 0; r < 4; r++) {
            float gi, gf, gg, go;
            unpack2(a0[2*r],   gi, gf);
            unpack2(a0[2*r+1], gg, go);
            float i_ = sigf(gi), f_ = sigf(gf), g_ = tanhf_fast(gg), o_ = sigf(go);
            c0[r] = f_ * c0[r] + i_ * g_;
            h0np[r] = o_ * tanhf_fast(c0[r]);
        }

        __syncthreads();   // all reads of s_h0/s_h1 for this step done
        *(float4*)&s_h0[ucol * RP + r0] = h0n;
        __syncthreads();   // new h0 visible

        // ---- phase 2: h0(new) @ W_ih1^T ----
        #pragma unroll 4
        for (int k = 0; k < H; k++) {
            ulonglong2 w = *(const ulonglong2*)&s_wih1[k * G + ucol * 4];
            float4 hv = *(const float4*)&s_h0[k * RP + r0];
            float hs[4] = {hv.x, hv.y, hv.z, hv.w};
            #pragma unroll
            for (int r = 0; r < 4; r++) {
                u64 hp = pack2(hs[r]);
                a1[2*r]   = ffma2(w.x, hp, a1[2*r]);
                a1[2*r+1] = ffma2(w.y, hp, a1[2*r+1]);
            }
        }

        // layer-1 cell update; phase 2 never reads s_h1, safe to write now
        float4 h1n;
        float* h1np = (float*)&h1n;
        #pragma unroll
        for (int r = 0; r < 4; r++) {
            float gi, gf, gg, go;
            unpack2(a1[2*r],   gi, gf);
            unpack2(a1[2*r+1], gg, go);
            float i_ = sigf(gi), f_ = sigf(gf), g_ = tanhf_fast(gg), o_ = sigf(go);
            c1[r] = f_ * c1[r] + i_ * g_;
            h1np[r] = o_ * tanhf_fast(c1[r]);
        }
        *(float4*)&s_h1[ucol * RP + r0] = h1n;
        __syncthreads();   // h1 complete before next step reads it
    }

    // ---- epilogue: out[b] = h1_last @ W_fc^T + b_fc (warp 0, lane = row) ----
    if (tid < 32) {
        float acc[OUT_D];
        #pragma unroll
        for (int o = 0; o < OUT_D; o++) acc[o] = s_bfc[o];
        #pragma unroll 8
        for (int k = 0; k < H; k++) {
            float hv = s_h1[k * RP + tid];   // h1[row=tid][k]
            #pragma unroll
            for (int o = 0; o < OUT_D; o++) acc[o] += hv * s_wfc[o * H + k];
        }
        int b = blockIdx.x * BTILE + tid;
        #pragma unroll
        for (int o = 0; o < OUT_D; o++)
            out[(size_t)b * OUT_D + o] = acc[o];
    }
}

extern "C" void kernel_launch(void* const* d_in, const int* in_sizes, int n_in,
                              void* d_out, int out_size)
{
    const float* x     = (const float*)d_in[0];
    const float* W_ih0 = (const float*)d_in[1];
    const float* W_hh0 = (const float*)d_in[2];
    const float* b_ih0 = (const float*)d_in[3];
    const float* b_hh0 = (const float*)d_in[4];
    const float* W_ih1 = (const float*)d_in[5];
    const float* W_hh1 = (const float*)d_in[6];
    const float* b_ih1 = (const float*)d_in[7];
    const float* b_hh1 = (const float*)d_in[8];
    const float* W_fc  = (const float*)d_in[9];
    const float* b_fc  = (const float*)d_in[10];
    float* out = (float*)d_out;

    const size_t smem_floats = (size_t)D_IN * G + 3 * (size_t)H * G + 2 * G
                             + OUT_D * H + 8 + 2 * (size_t)H * RP;
    const size_t smem_bytes = smem_floats * sizeof(float);   // ~225 KB

    cudaFuncSetAttribute(lstm_fused_kernel,
                         cudaFuncAttributeMaxDynamicSharedMemorySize,
                         (int)smem_bytes);

    lstm_fused_kernel<<<B_TOT / BTILE, NTHREADS, smem_bytes>>>(
        x, W_ih0, W_hh0, b_ih0, b_hh0,
        W_ih1, W_hh1, b_ih1, b_hh1, W_fc, b_fc, out);
}

// round 5
// speedup vs baseline: 2.0305x; 1.1269x over previous
#include <cuda_runtime.h>

// Problem constants
#define B_TOT    4096
#define T_LEN    512
#define D_IN     7
#define H        64
#define G        256      // 4*H gates per layer
#define OUT_D    4
#define BTILE    32       // batch rows per CTA
#define NTHREADS 256      // thread = (8 batch rows) x (1 unit = 4 gates)
#define RP       36       // h smem pitch in floats (conflict-free, 16B-aligned rows)
#define XP       32       // x smem pitch: s_x[d*XP + row]

typedef unsigned long long u64;

__device__ __forceinline__ u64 pack2(float v) {
    u64 r; asm("mov.b64 %0, {%1, %1};" : "=l"(r) : "f"(v)); return r;
}
__device__ __forceinline__ void unpack2(u64 v, float& a, float& b) {
    asm("mov.b64 {%0, %1}, %2;" : "=f"(a), "=f"(b) : "l"(v));
}
__device__ __forceinline__ u64 ffma2(u64 a, u64 b, u64 c) {
    u64 d; asm("fma.rn.f32x2 %0, %1, %2, %3;" : "=l"(d) : "l"(a), "l"(b), "l"(c)); return d;
}

__device__ __forceinline__ float sigf(float x) {
    return __fdividef(1.0f, 1.0f + __expf(-x));
}
__device__ __forceinline__ float tanhf_fast(float x) {
    return __fdividef(2.0f, 1.0f + __expf(-2.0f * x)) - 1.0f;
}

__global__ __launch_bounds__(NTHREADS, 1)
void lstm_fused_kernel(const float* __restrict__ x,
                       const float* __restrict__ W_ih0, const float* __restrict__ W_hh0,
                       const float* __restrict__ b_ih0, const float* __restrict__ b_hh0,
                       const float* __restrict__ W_ih1, const float* __restrict__ W_hh1,
                       const float* __restrict__ b_ih1, const float* __restrict__ b_hh1,
                       const float* __restrict__ W_fc,  const float* __restrict__ b_fc,
                       float* __restrict__ out)
{
    extern __shared__ float smem[];
    // weight layout: [k][unit][gate i,f,g,o] -> idx = k*256 + u*4 + g
    float* s_wih0 = smem;                    // [7][256]
    float* s_whh0 = s_wih0 + D_IN * G;       // [64][256]
    float* s_wih1 = s_whh0 + H * G;          // [64][256]
    float* s_whh1 = s_wih1 + H * G;          // [64][256]
    float* s_b0   = s_whh1 + H * G;          // [256]  combined bias [u][g]
    float* s_b1   = s_b0 + G;                // [256]
    float* s_wfc  = s_b1 + G;                // [4][64]
    float* s_bfc  = s_wfc + OUT_D * H;       // [8]
    float* s_h0   = s_bfc + 8;               // [64][RP]  h layer0, [unit][row]
    float* s_h1   = s_h0 + H * RP;           // [64][RP]
    float* s_x    = s_h1 + H * RP;           // [7][XP]   staged x[t], [d][row]

    const int tid  = threadIdx.x;
    const int urow = tid >> 6;               // 0..3 : batch-row group
    const int ucol = tid & 63;               // 0..63: hidden unit
    const int r0   = urow * 8;               // first of this thread's 8 rows

    // ---- stage weights into smem, transposed + gate-interleaved ----
    for (int idx = tid; idx < D_IN * G; idx += NTHREADS) {
        int d = idx >> 8, r = idx & 255, u = r >> 2, gb = r & 3;
        s_wih0[idx] = W_ih0[(gb * H + u) * D_IN + d];
    }
    for (int idx = tid; idx < H * G; idx += NTHREADS) {
        int k = idx >> 8, r = idx & 255, u = r >> 2, gb = r & 3;
        int row = gb * H + u;
        s_whh0[idx] = W_hh0[row * H + k];
        s_wih1[idx] = W_ih1[row * H + k];
        s_whh1[idx] = W_hh1[row * H + k];
    }
    for (int r = tid; r < G; r += NTHREADS) {
        int u = r >> 2, gb = r & 3, row = gb * H + u;
        s_b0[r] = b_ih0[row] + b_hh0[row];
        s_b1[r] = b_ih1[row] + b_hh1[row];
    }
    for (int i = tid; i < OUT_D * H; i += NTHREADS) s_wfc[i] = W_fc[i];
    if (tid < OUT_D) s_bfc[tid] = b_fc[tid];
    for (int i = tid; i < H * RP; i += NTHREADS) { s_h0[i] = 0.0f; s_h1[i] = 0.0f; }

    // x staging role: 224 threads each own one (row, d)
    const int  bb      = blockIdx.x * BTILE;
    const bool xactive = tid < BTILE * D_IN;
    const int  xrow    = tid / D_IN;
    const int  xd      = tid - xrow * D_IN;
    const float* xg    = x + ((size_t)(bb + xrow) * T_LEN) * D_IN + xd;

    // prestage x[0]
    if (xactive) s_x[xd * XP + xrow] = __ldg(xg);
    __syncthreads();

    // bias pairs for this thread's unit, held in regs across all steps
    u64 b0p0, b0p1, b1p0, b1p1;
    {
        ulonglong2 t0 = *(const ulonglong2*)&s_b0[ucol * 4];
        b0p0 = t0.x; b0p1 = t0.y;
        ulonglong2 t1 = *(const ulonglong2*)&s_b1[ucol * 4];
        b1p0 = t1.x; b1p1 = t1.y;
    }

    float c0[8], c1[8];
    #pragma unroll
    for (int r = 0; r < 8; r++) { c0[r] = 0.f; c1[r] = 0.f; }

    for (int t = 0; t < T_LEN; t++) {
        // accumulators: a0[2r]=(i,f), a0[2r+1]=(g,o) for row r0+r
        u64 a0[16], a1[16];
        #pragma unroll
        for (int r = 0; r < 8; r++) {
            a0[2*r] = b0p0; a0[2*r+1] = b0p1;
            a1[2*r] = b1p0; a1[2*r+1] = b1p1;
        }

        // ---- phase 1: h0 @ W_hh0^T and h1 @ W_hh1^T ----
        #pragma unroll 2
        for (int k = 0; k < H; k++) {
            ulonglong2 w0 = *(const ulonglong2*)&s_whh0[k * G + ucol * 4];
            ulonglong2 w1 = *(const ulonglong2*)&s_whh1[k * G + ucol * 4];
            float4 h0a = *(const float4*)&s_h0[k * RP + r0];
            float4 h0b = *(const float4*)&s_h0[k * RP + r0 + 4];
            float4 h1a = *(const float4*)&s_h1[k * RP + r0];
            float4 h1b = *(const float4*)&s_h1[k * RP + r0 + 4];
            float h0s[8] = {h0a.x, h0a.y, h0a.z, h0a.w, h0b.x, h0b.y, h0b.z, h0b.w};
            float h1s[8] = {h1a.x, h1a.y, h1a.z, h1a.w, h1b.x, h1b.y, h1b.z, h1b.w};
            #pragma unroll
            for (int r = 0; r < 8; r++) {
                u64 h0p = pack2(h0s[r]);
                a0[2*r]   = ffma2(w0.x, h0p, a0[2*r]);
                a0[2*r+1] = ffma2(w0.y, h0p, a0[2*r+1]);
                u64 h1p = pack2(h1s[r]);
                a1[2*r]   = ffma2(w1.x, h1p, a1[2*r]);
                a1[2*r+1] = ffma2(w1.y, h1p, a1[2*r+1]);
            }
        }

        // x @ W_ih0^T (x[t] staged in smem)
        #pragma unroll
        for (int d = 0; d < D_IN; d++) {
            ulonglong2 w = *(const ulonglong2*)&s_wih0[d * G + ucol * 4];
            float4 xa = *(const float4*)&s_x[d * XP + r0];
            float4 xb = *(const float4*)&s_x[d * XP + r0 + 4];
            float xs[8] = {xa.x, xa.y, xa.z, xa.w, xb.x, xb.y, xb.z, xb.w};
            #pragma unroll
            for (int r = 0; r < 8; r++) {
                u64 xp = pack2(xs[r]);
                a0[2*r]   = ffma2(w.x, xp, a0[2*r]);
                a0[2*r+1] = ffma2(w.y, xp, a0[2*r+1]);
            }
        }

        // layer-0 cell update for 8 rows of unit ucol
        float4 h0n0, h0n1;
        float* h0np = (float*)&h0n0;   // h0n0,h0n1 contiguous via array trick below
        float h0nv[8];
        #pragma unroll
        for (int r = 0; r < 8; r++) {
            float gi, gf, gg, go;
            unpack2(a0[2*r],   gi, gf);
            unpack2(a0[2*r+1], gg, go);
            float i_ = sigf(gi), f_ = sigf(gf), g_ = tanhf_fast(gg), o_ = sigf(go);
            c0[r] = f_ * c0[r] + i_ * g_;
            h0nv[r] = o_ * tanhf_fast(c0[r]);
        }
        h0n0 = make_float4(h0nv[0], h0nv[1], h0nv[2], h0nv[3]);
        h0n1 = make_float4(h0nv[4], h0nv[5], h0nv[6], h0nv[7]);
        (void)h0np;

        __syncthreads();   // all reads of s_h0/s_h1/s_x for this step done
        *(float4*)&s_h0[ucol * RP + r0]     = h0n0;
        *(float4*)&s_h0[ucol * RP + r0 + 4] = h0n1;
        __syncthreads();   // new h0 visible

        // ---- phase 2: h0(new) @ W_ih1^T ----
        #pragma unroll 2
        for (int k = 0; k < H; k++) {
            ulonglong2 w = *(const ulonglong2*)&s_wih1[k * G + ucol * 4];
            float4 ha = *(const float4*)&s_h0[k * RP + r0];
            float4 hb = *(const float4*)&s_h0[k * RP + r0 + 4];
            float hs[8] = {ha.x, ha.y, ha.z, ha.w, hb.x, hb.y, hb.z, hb.w};
            #pragma unroll
            for (int r = 0; r < 8; r++) {
                u64 hp = pack2(hs[r]);
                a1[2*r]   = ffma2(w.x, hp, a1[2*r]);
                a1[2*r+1] = ffma2(w.y, hp, a1[2*r+1]);
            }
        }

        // layer-1 cell update; phase 2 never reads s_h1, safe to write now
        float h1nv[8];
        #pragma unroll
        for (int r = 0; r < 8; r++) {
            float gi, gf, gg, go;
            unpack2(a1[2*r],   gi, gf);
            unpack2(a1[2*r+1], gg, go);
            float i_ = sigf(gi), f_ = sigf(gf), g_ = tanhf_fast(gg), o_ = sigf(go);
            c1[r] = f_ * c1[r] + i_ * g_;
            h1nv[r] = o_ * tanhf_fast(c1[r]);
        }
        *(float4*)&s_h1[ucol * RP + r0]     = make_float4(h1nv[0], h1nv[1], h1nv[2], h1nv[3]);
        *(float4*)&s_h1[ucol * RP + r0 + 4] = make_float4(h1nv[4], h1nv[5], h1nv[6], h1nv[7]);

        // stage x[t+1] (consumed after next sync; s_x readers finished pre-sync1)
        if (xactive && t + 1 < T_LEN)
            s_x[xd * XP + xrow] = __ldg(xg + (size_t)(t + 1) * D_IN);

        __syncthreads();   // h1 + x[t+1] complete before next step reads them
    }

    // ---- epilogue: out[b] = h1_last @ W_fc^T + b_fc (warp 0, lane = row) ----
    if (tid < 32) {
        float acc[OUT_D];
        #pragma unroll
        for (int o = 0; o < OUT_D; o++) acc[o] = s_bfc[o];
        #pragma unroll 8
        for (int k = 0; k < H; k++) {
            float hv = s_h1[k * RP + tid];   // h1[row=tid][k]
            #pragma unroll
            for (int o = 0; o < OUT_D; o++) acc[o] += hv * s_wfc[o * H + k];
        }
        int b = bb + tid;
        #pragma unroll
        for (int o = 0; o < OUT_D; o++)
            out[(size_t)b * OUT_D + o] = acc[o];
    }
}

extern "C" void kernel_launch(void* const* d_in, const int* in_sizes, int n_in,
                              void* d_out, int out_size)
{
    const float* x     = (const float*)d_in[0];
    const float* W_ih0 = (const float*)d_in[1];
    const float* W_hh0 = (const float*)d_in[2];
    const float* b_ih0 = (const float*)d_in[3];
    const float* b_hh0 = (const float*)d_in[4];
    const float* W_ih1 = (const float*)d_in[5];
    const float* W_hh1 = (const float*)d_in[6];
    const float* b_ih1 = (const float*)d_in[7];
    const float* b_hh1 = (const float*)d_in[8];
    const float* W_fc  = (const float*)d_in[9];
    const float* b_fc  = (const float*)d_in[10];
    float* out = (float*)d_out;

    const size_t smem_floats = (size_t)D_IN * G + 3 * (size_t)H * G + 2 * G
                             + OUT_D * H + 8 + 2 * (size_t)H * RP + D_IN * XP;
    const size_t smem_bytes = smem_floats * sizeof(float);   // 226,208 B

    cudaFuncSetAttribute(lstm_fused_kernel,
                         cudaFuncAttributeMaxDynamicSharedMemorySize,
                         (int)smem_bytes);

    lstm_fused_kernel<<<B_TOT / BTILE, NTHREADS, smem_bytes>>>(
        x, W_ih0, W_hh0, b_ih0, b_hh0,
        W_ih1, W_hh1, b_ih1, b_hh1, W_fc, b_fc, out);
}